// round 2
// baseline (speedup 1.0000x reference)
#include <cuda_runtime.h>
#include <cstddef>

// Problem constants
#define Nn   128
#define Lq   2048
#define NBat 2
#define Tc   64          // chunk length
#define NCH  32          // chunks per batch (Lq / Tc)

// Persistent device scratch (no allocations allowed)
__device__ float g_AdT[Nn * Nn];   // AdT[m*128 + k] = Ad[k][m]   (transposed for coalesced matvec)
__device__ float g_Bd[Nn];
__device__ float g_W0[Nn * Nn];    // squaring ping-pong (transposed rep)
__device__ float g_W1[Nn * Nn];    // final: (Ad^64)^T
__device__ float g_lfin[NBat * NCH * Nn];  // chunk-local end states (zero-init scan)
__device__ float g_s[NBat * NCH * Nn];     // true entering state per chunk

// ---------------------------------------------------------------------------
// Kernel 1: bilinear discretization via forward substitution.
// P = I - 0.5*A is LOWER TRIANGULAR (HiPPO-LegS A is lower triangular).
// Solve P * x = r for 129 right-hand sides: columns of (I + 0.5*A) -> Ad,
// and B -> Bd. One warp per column.
// ---------------------------------------------------------------------------
__global__ void k_solve(const float* __restrict__ A, const float* __restrict__ Bv) {
    __shared__ float x[Nn];
    const int c    = blockIdx.x;    // 0..127: Ad column; 128: Bd
    const int lane = threadIdx.x;

    for (int i = 0; i < Nn; i++) {
        // S = sum_{j<i} P[i][j] * x[j],  P[i][j] = -0.5*A[i][j] for j < i
        float p = 0.f;
        for (int j = lane; j < i; j += 32)
            p += (-0.5f * A[i * Nn + j]) * x[j];
        #pragma unroll
        for (int o = 16; o; o >>= 1) p += __shfl_down_sync(0xffffffffu, p, o);
        if (lane == 0) {
            float r = (c < Nn) ? ((i == c ? 1.f : 0.f) + 0.5f * A[i * Nn + c])
                               : Bv[i];
            float piv = 1.f - 0.5f * A[i * Nn + i];
            x[i] = (r - p) / piv;
        }
        __syncwarp();
    }
    if (c < Nn) {
        for (int i = lane; i < Nn; i += 32) g_AdT[c * Nn + i] = x[i];  // AdT[c][i] = Ad[i][c]
    } else {
        for (int i = lane; i < Nn; i += 32) g_Bd[i] = x[i];
    }
}

// ---------------------------------------------------------------------------
// Kernel 2: 128x128 matrix squaring (on the transposed rep: (M^T)^2 = (M^2)^T).
// mode 0: AdT->W0, mode 1: W0->W1, mode 2: W1->W0.
// Launch sequence 0,1,2,1,2,1 leaves (Ad^64)^T in W1.
// ---------------------------------------------------------------------------
__global__ void k_sq(int mode) {
    const float* S;
    float* D;
    if (mode == 0)      { S = g_AdT; D = g_W0; }
    else if (mode == 1) { S = g_W0;  D = g_W1; }
    else                { S = g_W1;  D = g_W0; }

    __shared__ float row[Nn];
    const int r = blockIdx.x, c = threadIdx.x;
    row[c] = S[r * Nn + c];
    __syncthreads();
    float acc = 0.f;
    #pragma unroll 16
    for (int j = 0; j < Nn; j++) acc += row[j] * S[j * Nn + c];
    D[r * Nn + c] = acc;
}

// ---------------------------------------------------------------------------
// Kernel 3: phase 1 — per-chunk zero-init local scan, keep chunk-end state.
// grid = 64 blocks (batch*chunk), block = 256 threads:
//   k = tid & 127 (output row), h = tid >> 7 (m-range half).
// Thread holds 64 Ad entries in registers (AdT[m][k] for its m-half).
// ---------------------------------------------------------------------------
__global__ void k_phase1(const float* __restrict__ f) {
    const int b = blockIdx.x >> 5, g = blockIdx.x & 31;
    const int tid = threadIdx.x, k = tid & 127, h = tid >> 7;
    __shared__ float csh[Nn];
    __shared__ float psh[Nn];
    __shared__ float fsh[Tc];

    float a[64];
    const int m0 = h * 64;
    #pragma unroll
    for (int j = 0; j < 64; j++) a[j] = g_AdT[(m0 + j) * Nn + k];
    const float bd = g_Bd[k];
    if (tid < Tc) fsh[tid] = f[b * Lq + g * Tc + tid];
    if (h == 0) csh[k] = 0.f;
    __syncthreads();

    float cn = 0.f;
    for (int d = 0; d < Tc; d++) {
        float acc = 0.f;
        #pragma unroll
        for (int j = 0; j < 64; j++) acc += a[j] * csh[m0 + j];
        if (h == 0) acc += bd * fsh[d];
        if (h == 1) psh[k] = acc;
        __syncthreads();
        if (h == 0) { cn = acc + psh[k]; csh[k] = cn; }
        __syncthreads();
    }
    if (h == 0) g_lfin[(b * NCH + g) * Nn + k] = cn;
}

// ---------------------------------------------------------------------------
// Kernel 4: phase 2 — sequential chunk-boundary combine per batch:
//   s_0 = 0; s_{g+1} = Ad^64 * s_g + lfin_g.   grid = 2 blocks.
// ---------------------------------------------------------------------------
__global__ void k_phase2() {
    const int b = blockIdx.x;
    const int tid = threadIdx.x, k = tid & 127, h = tid >> 7;
    __shared__ float csh[Nn];
    __shared__ float psh[Nn];

    float a[64];
    const int m0 = h * 64;
    #pragma unroll
    for (int j = 0; j < 64; j++) a[j] = g_W1[(m0 + j) * Nn + k];
    if (h == 0) { csh[k] = 0.f; g_s[(b * NCH) * Nn + k] = 0.f; }
    __syncthreads();

    for (int g = 1; g < NCH; g++) {
        float acc = 0.f;
        #pragma unroll
        for (int j = 0; j < 64; j++) acc += a[j] * csh[m0 + j];
        if (h == 1) psh[k] = acc;
        __syncthreads();
        if (h == 0) {
            float cn = acc + psh[k] + g_lfin[(b * NCH + g - 1) * Nn + k];
            csh[k] = cn;
            g_s[(b * NCH + g) * Nn + k] = cn;
        }
        __syncthreads();
    }
}

// ---------------------------------------------------------------------------
// Kernel 5: phase 3 — re-run each chunk from its true entering state and
// stream the broadcast output y[b,t,n,k] = C[n]*c[b,t,k] + D*f[b,t]
// (64 KB per time step) directly to GMEM. Also writes c_fin.
// grid = 64 blocks, 256 threads. Store path: each warp writes one full
// 512B output row per inner iteration — fully coalesced STG.128.
// ---------------------------------------------------------------------------
__global__ void k_phase3(const float* __restrict__ f, const float* __restrict__ C,
                         const float* __restrict__ Dv, float* __restrict__ out) {
    const int b = blockIdx.x >> 5, g = blockIdx.x & 31;
    const int tid = threadIdx.x, k = tid & 127, h = tid >> 7;
    const int wid = tid >> 5, lane = tid & 31;
    __shared__ float csh[Nn];
    __shared__ float psh[Nn];
    __shared__ float fsh[Tc];
    __shared__ float Csh[Nn];

    float a[64];
    const int m0 = h * 64;
    #pragma unroll
    for (int j = 0; j < 64; j++) a[j] = g_AdT[(m0 + j) * Nn + k];
    const float bd = g_Bd[k];
    if (tid < Tc) fsh[tid] = f[b * Lq + g * Tc + tid];
    if (tid < Nn) Csh[tid] = C[tid];
    if (h == 0) csh[k] = g_s[(b * NCH + g) * Nn + k];
    const float D0 = Dv[0];
    __syncthreads();

    const float4* c4 = (const float4*)csh;
    for (int d = 0; d < Tc; d++) {
        float acc = 0.f;
        #pragma unroll
        for (int j = 0; j < 64; j++) acc += a[j] * csh[m0 + j];
        if (h == 0) acc += bd * fsh[d];
        if (h == 1) psh[k] = acc;
        __syncthreads();
        if (h == 0) csh[k] = acc + psh[k];
        __syncthreads();

        // Emit the 128x128 y-block for t = g*Tc + d.
        const int t = g * Tc + d;
        const float Df = D0 * fsh[d];
        float4* dst = (float4*)(out + 256 + ((size_t)(b * Lq + t) << 14));
        #pragma unroll
        for (int it = 0; it < 16; it++) {
            const int n = it * 8 + wid;       // warp writes one full row n
            const float Cn = Csh[n];
            float4 cv = c4[lane];
            float4 v;
            v.x = fmaf(Cn, cv.x, Df);
            v.y = fmaf(Cn, cv.y, Df);
            v.z = fmaf(Cn, cv.z, Df);
            v.w = fmaf(Cn, cv.w, Df);
            dst[n * 32 + lane] = v;
        }
    }
    // c_fin = state after t = L-1 (last chunk only)
    if (h == 0 && g == NCH - 1) out[b * Nn + k] = csh[k];
}

// ---------------------------------------------------------------------------
// Launch: f, A, B, C, D in metadata order. out = [c_fin (256) | ys (2*2048*128*128)]
// ---------------------------------------------------------------------------
extern "C" void kernel_launch(void* const* d_in, const int* in_sizes, int n_in,
                              void* d_out, int out_size) {
    const float* f  = (const float*)d_in[0];
    const float* A  = (const float*)d_in[1];
    const float* Bv = (const float*)d_in[2];
    const float* C  = (const float*)d_in[3];
    const float* Dv = (const float*)d_in[4];
    float* out = (float*)d_out;

    k_solve<<<129, 32>>>(A, Bv);
    // Ad^2, Ad^4, Ad^8, Ad^16, Ad^32, Ad^64 (transposed rep); result in g_W1
    k_sq<<<128, 128>>>(0);
    k_sq<<<128, 128>>>(1);
    k_sq<<<128, 128>>>(2);
    k_sq<<<128, 128>>>(1);
    k_sq<<<128, 128>>>(2);
    k_sq<<<128, 128>>>(1);
    k_phase1<<<NBat * NCH, 256>>>(f);
    k_phase2<<<NBat, 256>>>();
    k_phase3<<<NBat * NCH, 256>>>(f, C, Dv, out);
}

// round 4
// speedup vs baseline: 1.1793x; 1.1793x over previous
#include <cuda_runtime.h>
#include <cstddef>

#define Nn   128
#define Lq   2048
#define NBat 2
#define Tc   64
#define NCH  32

// Persistent device scratch
__device__ float g_AdT[Nn * Nn];             // AdT[m][k] = Ad[k][m]
__device__ float g_Bd[Nn];
__device__ float g_W0[Nn * Nn];
__device__ float g_W1[Nn * Nn];              // final: (Ad^64)^T rep
__device__ float g_lfin[NBat * NCH * Nn];
__device__ float g_s[NBat * NCH * Nn];
__device__ float g_c[NBat * Lq * Nn];        // all states (2 MB)

// ---------------------------------------------------------------------------
// Kernel 1: bilinear discretization, right-looking forward substitution.
// P = I - 0.5*A lower triangular. 129 blocks (128 Ad columns + Bd), 128 thr.
// Thread i owns row i; after x[j] is published, all i>j fold it in.
// A staged in padded smem (stride 129 -> conflict-free strided reads).
// ---------------------------------------------------------------------------
__global__ void k_solve(const float* __restrict__ A, const float* __restrict__ Bv) {
    extern __shared__ float sh[];            // [128*129] A padded + [128] x
    float* Ash = sh;
    float* x   = sh + Nn * 129;
    const int c = blockIdx.x, i = threadIdx.x;

    for (int idx = i; idx < Nn * Nn; idx += Nn) {
        int r = idx >> 7, cc = idx & 127;
        Ash[r * 129 + cc] = A[idx];
    }
    __syncthreads();

    float r   = (c < Nn) ? ((i == c ? 1.f : 0.f) + 0.5f * Ash[i * 129 + c]) : Bv[i];
    float piv = 1.f - 0.5f * Ash[i * 129 + i];
    float acc = 0.f;
    for (int j = 0; j < Nn; j++) {
        if (i == j) x[j] = (r - acc) / piv;
        __syncthreads();
        if (i > j) acc = fmaf(-0.5f * Ash[i * 129 + j], x[j], acc);
    }
    if (c < Nn) g_AdT[c * Nn + i] = x[i];
    else        g_Bd[i]           = x[i];
}

// ---------------------------------------------------------------------------
// Kernel 2: 128x128 squaring with full matrix staged in smem.
// 32 blocks x 512 threads, 4 rows per block, 4 accumulators.
// Sequence 0,1,2,1,2,1 leaves (Ad^64)^T in g_W1.
// ---------------------------------------------------------------------------
__global__ void k_sq(int mode) {
    extern __shared__ float Ssh[];           // 16384 floats = 64 KB
    const float* S; float* D;
    if (mode == 0)      { S = g_AdT; D = g_W0; }
    else if (mode == 1) { S = g_W0;  D = g_W1; }
    else                { S = g_W1;  D = g_W0; }

    const int tid = threadIdx.x;
    float4* s4 = (float4*)Ssh;
    const float4* g4 = (const float4*)S;
    #pragma unroll
    for (int idx = tid; idx < Nn * Nn / 4; idx += 512) s4[idx] = g4[idx];
    __syncthreads();

    const int r = (blockIdx.x << 2) + (tid >> 7);
    const int col = tid & 127;
    const float* rp = Ssh + r * Nn;
    float a0 = 0.f, a1 = 0.f, a2 = 0.f, a3 = 0.f;
    #pragma unroll 8
    for (int j = 0; j < Nn; j += 4) {
        a0 = fmaf(rp[j    ], Ssh[(j    ) * Nn + col], a0);
        a1 = fmaf(rp[j + 1], Ssh[(j + 1) * Nn + col], a1);
        a2 = fmaf(rp[j + 2], Ssh[(j + 2) * Nn + col], a2);
        a3 = fmaf(rp[j + 3], Ssh[(j + 3) * Nn + col], a3);
    }
    D[r * Nn + col] = (a0 + a1) + (a2 + a3);
}

// ---------------------------------------------------------------------------
// Scan step helper layout (phase1 / phase2 / states):
// 256 threads: k = tid&127 output row, h = tid>>7 half of m-range.
// Thread holds 64 AdT entries in registers; csh read as float4 broadcast.
// ---------------------------------------------------------------------------
__device__ __forceinline__ float scan_dot(const float* __restrict__ a,
                                          const float4* __restrict__ c4) {
    float a0 = 0.f, a1 = 0.f, a2 = 0.f, a3 = 0.f;
    #pragma unroll
    for (int jj = 0; jj < 16; jj++) {
        float4 cv = c4[jj];
        a0 = fmaf(a[4 * jj    ], cv.x, a0);
        a1 = fmaf(a[4 * jj + 1], cv.y, a1);
        a2 = fmaf(a[4 * jj + 2], cv.z, a2);
        a3 = fmaf(a[4 * jj + 3], cv.w, a3);
    }
    return (a0 + a1) + (a2 + a3);
}

// Kernel 3: phase 1 — per-chunk zero-init local scan, keep chunk-end state.
__global__ void k_phase1(const float* __restrict__ f) {
    const int b = blockIdx.x >> 5, g = blockIdx.x & 31;
    const int tid = threadIdx.x, k = tid & 127, h = tid >> 7;
    __shared__ float csh[Nn];
    __shared__ float psh[Nn];
    __shared__ float fsh[Tc];

    float a[64];
    const int m0 = h * 64;
    #pragma unroll
    for (int j = 0; j < 64; j++) a[j] = g_AdT[(m0 + j) * Nn + k];
    const float bd = g_Bd[k];
    if (tid < Tc) fsh[tid] = f[b * Lq + g * Tc + tid];
    if (h == 0) csh[k] = 0.f;
    __syncthreads();

    const float4* c4 = (const float4*)(csh + m0);
    float cn = 0.f;
    for (int d = 0; d < Tc; d++) {
        float acc = scan_dot(a, c4);
        if (h == 0) acc = fmaf(bd, fsh[d], acc);
        if (h == 1) psh[k] = acc;
        __syncthreads();
        if (h == 0) { cn = acc + psh[k]; csh[k] = cn; }
        __syncthreads();
    }
    if (h == 0) g_lfin[(b * NCH + g) * Nn + k] = cn;
}

// Kernel 4: phase 2 — sequential chunk-boundary combine: s_{g+1} = Ad^64 s_g + lfin_g.
__global__ void k_phase2() {
    const int b = blockIdx.x;
    const int tid = threadIdx.x, k = tid & 127, h = tid >> 7;
    __shared__ float csh[Nn];
    __shared__ float psh[Nn];

    float a[64];
    const int m0 = h * 64;
    #pragma unroll
    for (int j = 0; j < 64; j++) a[j] = g_W1[(m0 + j) * Nn + k];
    if (h == 0) { csh[k] = 0.f; g_s[(b * NCH) * Nn + k] = 0.f; }
    __syncthreads();

    const float4* c4 = (const float4*)(csh + m0);
    for (int g = 1; g < NCH; g++) {
        float acc = scan_dot(a, c4);
        if (h == 1) psh[k] = acc;
        __syncthreads();
        if (h == 0) {
            float cn = acc + psh[k] + g_lfin[(b * NCH + g - 1) * Nn + k];
            csh[k] = cn;
            g_s[(b * NCH + g) * Nn + k] = cn;
        }
        __syncthreads();
    }
}

// Kernel 5: states — rerun each chunk from its true entering state; write all
// states to g_c (2 MB) and c_fin to out[0:256).
__global__ void k_states(const float* __restrict__ f, float* __restrict__ out) {
    const int b = blockIdx.x >> 5, g = blockIdx.x & 31;
    const int tid = threadIdx.x, k = tid & 127, h = tid >> 7;
    __shared__ float csh[Nn];
    __shared__ float psh[Nn];
    __shared__ float fsh[Tc];

    float a[64];
    const int m0 = h * 64;
    #pragma unroll
    for (int j = 0; j < 64; j++) a[j] = g_AdT[(m0 + j) * Nn + k];
    const float bd = g_Bd[k];
    if (tid < Tc) fsh[tid] = f[b * Lq + g * Tc + tid];
    if (h == 0) csh[k] = g_s[(b * NCH + g) * Nn + k];
    __syncthreads();

    const float4* c4 = (const float4*)(csh + m0);
    float cn = 0.f;
    for (int d = 0; d < Tc; d++) {
        float acc = scan_dot(a, c4);
        if (h == 0) acc = fmaf(bd, fsh[d], acc);
        if (h == 1) psh[k] = acc;
        __syncthreads();
        if (h == 0) {
            cn = acc + psh[k];
            csh[k] = cn;
            g_c[(size_t)(b * Lq + g * Tc + d) * Nn + k] = cn;
        }
        __syncthreads();
    }
    if (h == 0 && g == NCH - 1) out[b * Nn + k] = cn;
}

// Kernel 6: broadcast — full-grid, pure-BW emission of
// y[b,t,n,k] = C[n]*c[b,t,k] + D*f[b,t].  4096 blocks, one (b,t) each.
__global__ void k_bcast(const float* __restrict__ C, const float* __restrict__ Dv,
                        const float* __restrict__ f, float* __restrict__ out) {
    const int bt = blockIdx.x;               // b*2048 + t
    const int tid = threadIdx.x, wid = tid >> 5, lane = tid & 31;
    __shared__ float csh[Nn];
    __shared__ float Csh[Nn];
    if (tid < Nn) {
        csh[tid] = g_c[(size_t)bt * Nn + tid];
        Csh[tid] = C[tid];
    }
    const float Df = Dv[0] * f[bt];
    __syncthreads();

    const float4 cv = ((const float4*)csh)[lane];
    float4* dst = (float4*)(out + 256 + ((size_t)bt << 14));
    #pragma unroll
    for (int it = 0; it < 16; it++) {
        const int n = it * 8 + wid;          // warp writes one full 512B row
        const float Cn = Csh[n];
        float4 v;
        v.x = fmaf(Cn, cv.x, Df);
        v.y = fmaf(Cn, cv.y, Df);
        v.z = fmaf(Cn, cv.z, Df);
        v.w = fmaf(Cn, cv.w, Df);
        dst[n * 32 + lane] = v;
    }
}

extern "C" void kernel_launch(void* const* d_in, const int* in_sizes, int n_in,
                              void* d_out, int out_size) {
    const float* f  = (const float*)d_in[0];
    const float* A  = (const float*)d_in[1];
    const float* Bv = (const float*)d_in[2];
    const float* C  = (const float*)d_in[3];
    const float* Dv = (const float*)d_in[4];
    float* out = (float*)d_out;

    const int solve_smem = (Nn * 129 + Nn) * (int)sizeof(float);   // 66560
    const int sq_smem    = Nn * Nn * (int)sizeof(float);           // 65536
    cudaFuncSetAttribute(k_solve, cudaFuncAttributeMaxDynamicSharedMemorySize, solve_smem);
    cudaFuncSetAttribute(k_sq,    cudaFuncAttributeMaxDynamicSharedMemorySize, sq_smem);

    k_solve<<<129, 128, solve_smem>>>(A, Bv);
    k_sq<<<32, 512, sq_smem>>>(0);   // Ad^2
    k_sq<<<32, 512, sq_smem>>>(1);   // Ad^4
    k_sq<<<32, 512, sq_smem>>>(2);   // Ad^8
    k_sq<<<32, 512, sq_smem>>>(1);   // Ad^16
    k_sq<<<32, 512, sq_smem>>>(2);   // Ad^32
    k_sq<<<32, 512, sq_smem>>>(1);   // Ad^64 -> g_W1
    k_phase1<<<NBat * NCH, 256>>>(f);
    k_phase2<<<NBat, 256>>>();
    k_states<<<NBat * NCH, 256>>>(f, out);
    k_bcast<<<NBat * Lq, 256>>>(C, Dv, f, out);
}

// round 6
// speedup vs baseline: 1.7566x; 1.4896x over previous
#include <cuda_runtime.h>
#include <cstddef>

#define Nn   128
#define Lq   2048
#define NBat 2
#define Tc   64
#define NCH  32
#define NBLK 64          // fused kernel grid (co-resident, 1 block/SM)
#define NBAR 9

// Persistent device scratch
__device__ float g_AdT[Nn * Nn];             // AdT[m][k] = Ad[k][m]
__device__ float g_Bd[Nn];
__device__ float g_W0[Nn * Nn];
__device__ float g_W1[Nn * Nn];              // final: (Ad^64)^T rep
__device__ float g_lfin[NBat * NCH * Nn];
__device__ float g_s[NBat * NCH * Nn];
__device__ float g_c[NBat * Lq * Nn];        // all states (2 MB)
__device__ unsigned int g_bar[NBAR];         // one-shot barrier slots

// ---------------------------------------------------------------------------
// Reset barrier slots (runs before fused kernel on the same stream).
// ---------------------------------------------------------------------------
__global__ void k_reset() {
    if (threadIdx.x < NBAR) g_bar[threadIdx.x] = 0u;
}

// One-shot grid barrier: slot idx used exactly once per launch.
__device__ __forceinline__ void gbar(int idx) {
    __syncthreads();
    if (threadIdx.x == 0) {
        __threadfence();
        atomicAdd(&g_bar[idx], 1u);
        while (*(volatile unsigned int*)&g_bar[idx] < (unsigned)NBLK) {
            __nanosleep(64);
        }
        __threadfence();
    }
    __syncthreads();
}

__device__ __forceinline__ float scan_dot(const float* __restrict__ a,
                                          const float4* __restrict__ c4) {
    float a0 = 0.f, a1 = 0.f, a2 = 0.f, a3 = 0.f;
    #pragma unroll
    for (int jj = 0; jj < 16; jj++) {
        float4 cv = c4[jj];
        a0 = fmaf(a[4 * jj    ], cv.x, a0);
        a1 = fmaf(a[4 * jj + 1], cv.y, a1);
        a2 = fmaf(a[4 * jj + 2], cv.z, a2);
        a3 = fmaf(a[4 * jj + 3], cv.w, a3);
    }
    return (a0 + a1) + (a2 + a3);
}

// ---------------------------------------------------------------------------
// Fused prelude: solve -> phase1 -> 6 squarings -> phase2 -> states.
// 64 blocks x 256 threads, dyn smem 67072 B (1 block/SM, all co-resident).
// ---------------------------------------------------------------------------
__global__ void __launch_bounds__(256, 1)
k_fused(const float* __restrict__ A, const float* __restrict__ Bv,
        const float* __restrict__ f, float* __restrict__ out) {
    extern __shared__ float sh[];            // max(128*129 + 256, 128*128) floats
    const int bid = blockIdx.x, tid = threadIdx.x;
    const int k = tid & 127, h = tid >> 7;   // k: output row, h: m-half
    const int m0 = h * 64;

    __shared__ float csh[Nn];
    __shared__ float psh[Nn];
    __shared__ float fsh[Tc];

    // ===== Stage A: bilinear discretization (forward substitution) =====
    // P = I - 0.5A lower-triangular; solve 128 Ad columns + Bd.
    {
        float* Ash = sh;                     // padded stride 129
        float* x   = sh + Nn * 129;         // 2 halves x 128
        for (int idx = tid; idx < Nn * Nn; idx += 256)
            Ash[(idx >> 7) * 129 + (idx & 127)] = A[idx];
        __syncthreads();

        const int i = k;
        for (int round = 0; round < 2; round++) {
            if (round == 1 && bid != 0) break;
            const int col  = (round == 0) ? (bid * 2 + h) : (h == 0 ? Nn : 0);
            const bool doStore = (round == 0) || (h == 0);
            float* xh = x + h * Nn;
            float r   = (col < Nn) ? ((i == col ? 1.f : 0.f) + 0.5f * Ash[i * 129 + col])
                                   : Bv[i];
            float piv = 1.f - 0.5f * Ash[i * 129 + i];
            float acc = 0.f;
            for (int j = 0; j < Nn; j++) {
                if (i == j) xh[j] = (r - acc) / piv;
                __syncthreads();
                if (i > j) acc = fmaf(-0.5f * Ash[i * 129 + j], xh[j], acc);
            }
            if (doStore) {
                if (col < Nn) g_AdT[col * Nn + i] = xh[i];
                else          g_Bd[i]             = xh[i];
            }
            __syncthreads();
        }
    }
    gbar(0);

    // ===== Stage B: phase 1 — per-chunk zero-init local scan =====
    const int b = bid >> 5, g = bid & 31;
    float a[64];
    #pragma unroll
    for (int j = 0; j < 64; j++) a[j] = g_AdT[(m0 + j) * Nn + k];
    float bd = g_Bd[k];
    {
        if (tid < Tc) fsh[tid] = f[b * Lq + g * Tc + tid];
        if (h == 0) csh[k] = 0.f;
        __syncthreads();
        const float4* c4 = (const float4*)(csh + m0);
        float cn = 0.f;
        for (int d = 0; d < Tc; d++) {
            float acc = scan_dot(a, c4);
            if (h == 0) acc = fmaf(bd, fsh[d], acc);
            if (h == 1) psh[k] = acc;
            __syncthreads();
            if (h == 0) { cn = acc + psh[k]; csh[k] = cn; }
            __syncthreads();
        }
        if (h == 0) g_lfin[(b * NCH + g) * Nn + k] = cn;
    }
    gbar(1);

    // ===== Stage C: six 128x128 squarings -> (Ad^64)^T in g_W1 =====
    {
        const int r = bid * 2 + h;           // output row
        #pragma unroll 1
        for (int s = 0; s < 6; s++) {
            const float* S = (s == 0) ? g_AdT : ((s & 1) ? g_W0 : g_W1);
            float*       D = (s & 1) ? g_W1 : g_W0;
            float4* s4 = (float4*)sh;
            const float4* g4 = (const float4*)S;
            for (int idx = tid; idx < Nn * Nn / 4; idx += 256) s4[idx] = g4[idx];
            __syncthreads();
            const float* rp = sh + r * Nn;
            float a0 = 0.f, a1 = 0.f, a2 = 0.f, a3 = 0.f;
            #pragma unroll 8
            for (int j = 0; j < Nn; j += 4) {
                a0 = fmaf(rp[j    ], sh[(j    ) * Nn + k], a0);
                a1 = fmaf(rp[j + 1], sh[(j + 1) * Nn + k], a1);
                a2 = fmaf(rp[j + 2], sh[(j + 2) * Nn + k], a2);
                a3 = fmaf(rp[j + 3], sh[(j + 3) * Nn + k], a3);
            }
            D[r * Nn + k] = (a0 + a1) + (a2 + a3);
            gbar(2 + s);
        }
    }

    // ===== Stage D: phase 2 — chunk-boundary combine (blocks 0,1) =====
    if (bid < NBat) {
        float w[64];
        #pragma unroll
        for (int j = 0; j < 64; j++) w[j] = g_W1[(m0 + j) * Nn + k];
        if (h == 0) { csh[k] = 0.f; g_s[(bid * NCH) * Nn + k] = 0.f; }
        __syncthreads();
        const float4* c4 = (const float4*)(csh + m0);
        for (int gg = 1; gg < NCH; gg++) {
            float acc = scan_dot(w, c4);
            if (h == 1) psh[k] = acc;
            __syncthreads();
            if (h == 0) {
                float cn = acc + psh[k] + g_lfin[(bid * NCH + gg - 1) * Nn + k];
                csh[k] = cn;
                g_s[(bid * NCH + gg) * Nn + k] = cn;
            }
            __syncthreads();
        }
        // restore a[] (clobbered register allocation is per-path; reload to be safe)
        #pragma unroll
        for (int j = 0; j < 64; j++) a[j] = g_AdT[(m0 + j) * Nn + k];
    }
    gbar(8);

    // ===== Stage E: states — rerun chunks from true entering state =====
    {
        if (tid < Tc) fsh[tid] = f[b * Lq + g * Tc + tid];
        if (h == 0) csh[k] = g_s[(b * NCH + g) * Nn + k];
        __syncthreads();
        const float4* c4 = (const float4*)(csh + m0);
        float cn = 0.f;
        for (int d = 0; d < Tc; d++) {
            float acc = scan_dot(a, c4);
            if (h == 0) acc = fmaf(bd, fsh[d], acc);
            if (h == 1) psh[k] = acc;
            __syncthreads();
            if (h == 0) {
                cn = acc + psh[k];
                csh[k] = cn;
                g_c[(size_t)(b * Lq + g * Tc + d) * Nn + k] = cn;
            }
            __syncthreads();
        }
        if (h == 0 && g == NCH - 1) out[b * Nn + k] = cn;
    }
}

// ---------------------------------------------------------------------------
// Broadcast: y[b,t,n,k] = C[n]*c[b,t,k] + D*f[b,t].  4096 blocks, one (b,t).
// ---------------------------------------------------------------------------
__global__ void k_bcast(const float* __restrict__ C, const float* __restrict__ Dv,
                        const float* __restrict__ f, float* __restrict__ out) {
    const int bt = blockIdx.x;
    const int tid = threadIdx.x, wid = tid >> 5, lane = tid & 31;
    __shared__ float csh[Nn];
    __shared__ float Csh[Nn];
    if (tid < Nn) {
        csh[tid] = g_c[(size_t)bt * Nn + tid];
        Csh[tid] = C[tid];
    }
    const float Df = Dv[0] * f[bt];
    __syncthreads();

    const float4 cv = ((const float4*)csh)[lane];
    float4* dst = (float4*)(out + 256 + ((size_t)bt << 14));
    #pragma unroll
    for (int it = 0; it < 16; it++) {
        const int n = it * 8 + wid;          // warp writes one full 512B row
        const float Cn = Csh[n];
        float4 v;
        v.x = fmaf(Cn, cv.x, Df);
        v.y = fmaf(Cn, cv.y, Df);
        v.z = fmaf(Cn, cv.z, Df);
        v.w = fmaf(Cn, cv.w, Df);
        dst[n * 32 + lane] = v;
    }
}

extern "C" void kernel_launch(void* const* d_in, const int* in_sizes, int n_in,
                              void* d_out, int out_size) {
    const float* f  = (const float*)d_in[0];
    const float* A  = (const float*)d_in[1];
    const float* Bv = (const float*)d_in[2];
    const float* C  = (const float*)d_in[3];
    const float* Dv = (const float*)d_in[4];
    float* out = (float*)d_out;

    const int fused_smem = (Nn * 129 + 2 * Nn) * (int)sizeof(float);  // 67072 B
    static int attr_set = 0;
    cudaFuncSetAttribute(k_fused, cudaFuncAttributeMaxDynamicSharedMemorySize, fused_smem);
    (void)attr_set;

    k_reset<<<1, 32>>>();
    k_fused<<<NBLK, 256, fused_smem>>>(A, Bv, f, out);
    k_bcast<<<NBat * Lq, 256>>>(C, Dv, f, out);
}